// round 4
// baseline (speedup 1.0000x reference)
#include <cuda_runtime.h>
#include <cstdint>

#define B_   64
#define T_   1024
#define F_   256
#define U_   512
#define G_   1536             // 3*U
#define P_   1024             // 2*U
#define GB_  (G_*B_)          // 98304
#define HB_  (U_*B_)          // 32768 floats per h ping-pong buffer
#define EPS_ 1e-3f

// ---------------------------------------------------------------------------
// Scratch: __device__ globals (allocation-free per harness rules)
// ---------------------------------------------------------------------------
__device__ float g_xwf[(size_t)T_ * G_ * B_];   // [T][G][B]  x@Wf + bi_f
__device__ float g_xwb[(size_t)T_ * G_ * B_];   // [T][G][B]  x@Wb + bi_b
__device__ float g_resid[(size_t)B_ * T_ * P_]; // [B*T][P]   x@Wp
__device__ float g_hf[(size_t)B_ * T_ * U_];    // [B][T][U]
__device__ float g_hb[(size_t)B_ * T_ * U_];    // [B][T][U]
__device__ float g_hbuf[2 * 2 * HB_];           // [dir][parity][U][B]
__device__ unsigned g_barc[2];                  // barrier arrive counters
__device__ unsigned g_barg[2];                  // barrier generations

// ---------------------------------------------------------------------------
// f32x2 packed FMA (Blackwell dual-fp32; only reachable via PTX)
// ---------------------------------------------------------------------------
__device__ __forceinline__ void fma2(float2& d, float2 a, float2 b) {
    unsigned long long& dd = reinterpret_cast<unsigned long long&>(d);
    unsigned long long& aa = reinterpret_cast<unsigned long long&>(a);
    unsigned long long& bb = reinterpret_cast<unsigned long long&>(b);
    asm("fma.rn.f32x2 %0, %1, %2, %0;" : "+l"(dd) : "l"(aa), "l"(bb));
}
__device__ __forceinline__ float2 dup2(float x) { return make_float2(x, x); }

// ---------------------------------------------------------------------------
// Init: zero h0 buffers + barrier state (graph replays reuse globals)
// ---------------------------------------------------------------------------
__global__ void init_kernel() {
    int idx = blockIdx.x * blockDim.x + threadIdx.x;
    int stride = gridDim.x * blockDim.x;
    for (int i = idx; i < 2 * 2 * HB_; i += stride) g_hbuf[i] = 0.0f;
    if (idx < 2) { g_barc[idx] = 0u; g_barg[idx] = 0u; }
}

// ---------------------------------------------------------------------------
// fp32 GEMM: A[BT,256] x Bw[256,N].  64x64 tile, BK=16, 256 threads.
//  mode 0 -> g_xwf [t][g][b] (+bias), mode 1 -> g_xwb, mode 2 -> g_resid [r][n]
// ---------------------------------------------------------------------------
__global__ void __launch_bounds__(256) gemm_kernel(
    const float* __restrict__ A, const float* __restrict__ Bw,
    const float* __restrict__ bias, int N, int mode)
{
    __shared__ float As[16][64];
    __shared__ float Bs[16][64];

    int tid  = threadIdx.x;
    int tx   = tid & 15;
    int ty   = tid >> 4;
    int row0 = blockIdx.x * 64;
    int col0 = blockIdx.y * 64;

    int lrow = tid >> 2;        // A: row within tile
    int lkq  = (tid & 3) * 4;   // A: k quad
    int lk   = tid >> 4;        // B: k row
    int lnq  = (tid & 15) * 4;  // B: col quad

    float2 acc[4][2];
#pragma unroll
    for (int i = 0; i < 4; i++) { acc[i][0] = make_float2(0.f, 0.f); acc[i][1] = make_float2(0.f, 0.f); }

    for (int k0 = 0; k0 < F_; k0 += 16) {
        float4 av = *(const float4*)(A + (size_t)(row0 + lrow) * F_ + k0 + lkq);
        As[lkq + 0][lrow] = av.x;
        As[lkq + 1][lrow] = av.y;
        As[lkq + 2][lrow] = av.z;
        As[lkq + 3][lrow] = av.w;
        *(float4*)(&Bs[lk][lnq]) = *(const float4*)(Bw + (size_t)(k0 + lk) * N + col0 + lnq);
        __syncthreads();

#pragma unroll
        for (int kk = 0; kk < 16; kk++) {
            float4 a4 = *(const float4*)(&As[kk][ty * 4]);
            float4 b4 = *(const float4*)(&Bs[kk][tx * 4]);
            float2 bp0 = make_float2(b4.x, b4.y);
            float2 bp1 = make_float2(b4.z, b4.w);
            float aa[4] = {a4.x, a4.y, a4.z, a4.w};
#pragma unroll
            for (int i = 0; i < 4; i++) {
                float2 ad = dup2(aa[i]);
                fma2(acc[i][0], ad, bp0);
                fma2(acc[i][1], ad, bp1);
            }
        }
        __syncthreads();
    }

    if (mode == 2) {
#pragma unroll
        for (int i = 0; i < 4; i++) {
            int r = row0 + ty * 4 + i;
            int c = col0 + tx * 4;
            g_resid[(size_t)r * P_ + c + 0] = acc[i][0].x;
            g_resid[(size_t)r * P_ + c + 1] = acc[i][0].y;
            g_resid[(size_t)r * P_ + c + 2] = acc[i][1].x;
            g_resid[(size_t)r * P_ + c + 3] = acc[i][1].y;
        }
    } else {
        float* outp = (mode == 1) ? g_xwb : g_xwf;
#pragma unroll
        for (int i = 0; i < 4; i++) {
            int r = row0 + ty * 4 + i;
            int b = r >> 10;       // r = b*1024 + t
            int t = r & 1023;
            int c = col0 + tx * 4;
            float v[4] = {acc[i][0].x, acc[i][0].y, acc[i][1].x, acc[i][1].y};
#pragma unroll
            for (int j = 0; j < 4; j++) {
                int g = c + j;
                outp[(size_t)t * GB_ + (size_t)g * B_ + b] = v[j] + bias[g];
            }
        }
    }
}

// ---------------------------------------------------------------------------
// Per-direction grid barrier (64 blocks each, all co-resident)
// ---------------------------------------------------------------------------
__device__ __forceinline__ void dir_barrier(int dir, unsigned target) {
    __syncthreads();
    if (threadIdx.x == 0) {
        __threadfence();
        unsigned prev = atomicAdd(&g_barc[dir], 1u);
        if (prev == 63u) {
            g_barc[dir] = 0u;
            __threadfence();
            atomicAdd(&g_barg[dir], 1u);
        } else {
            volatile unsigned* vg = &g_barg[dir];
            while (*vg < target) { __nanosleep(16); }
            __threadfence();
        }
    }
    __syncthreads();
}

// ---------------------------------------------------------------------------
// GRU recurrence v3. 128 blocks: 0..63 forward, 64..127 backward.
// Block owns 8 hidden units; 256 threads = 8 warps (2/SMSP).
// Warp w: partial dots for unit pair up=w>>1 over k-half kh=w&1.
// U slice stored in SMEM PRE-DUPLICATED as f32x2 pairs so one LDS.128 yields
// {u_k,u_k,u_{k+1},u_{k+1}} -- aligned operand pairs for fma.rn.f32x2, no MOVs.
// Dynamic smem: U dup 96KB + partials 12KB = 108KB.
// ---------------------------------------------------------------------------
__global__ void __launch_bounds__(256) gru_kernel(
    const float* __restrict__ Ufm, const float* __restrict__ Ubm,
    const float* __restrict__ bfv, const float* __restrict__ bbv)
{
    extern __shared__ float smem_[];
    float2* Us2 = (float2*)smem_;                       // [24][512] duplicated
    float2 (*part)[6][32] = (float2 (*)[6][32])(smem_ + 24 * 512 * 2);  // [8][6][32]

    int tid = threadIdx.x;
    int dir = blockIdx.x >> 6;
    int jb  = blockIdx.x & 63;

    const float* Um    = dir ? Ubm : Ufm;
    const float* brv   = (dir ? bbv : bfv) + G_;   // recurrent bias b[1]
    const float* xw    = dir ? g_xwb : g_xwf;
    float*       hout  = dir ? g_hb  : g_hf;
    float*       hbase = g_hbuf + (size_t)dir * 2 * HB_;

    // Load U slice duplicated: column c=(gate,uu) -> Um[:, gate*512 + jb*8 + uu]
    for (int idx = tid; idx < 24 * 512; idx += 256) {
        int c = idx >> 9;
        int k = idx & 511;
        int g  = c >> 3;
        int uu = c & 7;
        float v = Um[(size_t)k * G_ + g * U_ + jb * 8 + uu];
        Us2[c * 512 + k] = make_float2(v, v);
    }

    int w    = tid >> 5;
    int lane = tid & 31;
    int kh   = w & 1;          // k half: [kh*256, kh*256+256)
    int up   = w >> 1;         // unit pair 0..3
    int ul0  = up * 2, ul1 = ul0 + 1;

    // compute-role U pointers: float4 over duplicated pairs; 128 float4 per k-half
    const float4* UZ0 = (const float4*)(Us2 + (size_t)(0 * 8 + ul0) * 512 + kh * 256);
    const float4* UZ1 = (const float4*)(Us2 + (size_t)(0 * 8 + ul1) * 512 + kh * 256);
    const float4* UR0 = (const float4*)(Us2 + (size_t)(1 * 8 + ul0) * 512 + kh * 256);
    const float4* UR1 = (const float4*)(Us2 + (size_t)(1 * 8 + ul1) * 512 + kh * 256);
    const float4* UH0 = (const float4*)(Us2 + (size_t)(2 * 8 + ul0) * 512 + kh * 256);
    const float4* UH1 = (const float4*)(Us2 + (size_t)(2 * 8 + ul1) * 512 + kh * 256);

    // finalize-role (warps 0..3): units 2w, 2w+1
    int fug0 = jb * 8 + 2 * w;
    int fug1 = fug0 + 1;
    float brz0 = 0.f, brz1 = 0.f, brr0 = 0.f, brr1 = 0.f, brh0 = 0.f, brh1 = 0.f;
    if (w < 4) {
        brz0 = brv[fug0];          brz1 = brv[fug1];
        brr0 = brv[U_ + fug0];     brr1 = brv[U_ + fug1];
        brh0 = brv[2 * U_ + fug0]; brh1 = brv[2 * U_ + fug1];
    }

    __syncthreads();

    for (int s = 0; s < T_; s++) {
        int tt = dir ? (T_ - 1 - s) : s;

        int par = s & 1;
        const float2* Hc = (const float2*)(hbase + (size_t)par * HB_);
        float2*       Hn = (float2*)(hbase + (size_t)(par ^ 1) * HB_);

        // finalize warps prefetch input projections + previous h (indep of dots)
        float2 xz0, xz1, xr0, xr1, xh0, xh1, hold0, hold1;
        if (w < 4) {
            const float2* XW2 = (const float2*)(xw + (size_t)tt * GB_);
            xz0 = XW2[(size_t)(0 * U_ + fug0) * 32 + lane];
            xz1 = XW2[(size_t)(0 * U_ + fug1) * 32 + lane];
            xr0 = XW2[(size_t)(1 * U_ + fug0) * 32 + lane];
            xr1 = XW2[(size_t)(1 * U_ + fug1) * 32 + lane];
            xh0 = XW2[(size_t)(2 * U_ + fug0) * 32 + lane];
            xh1 = XW2[(size_t)(2 * U_ + fug1) * 32 + lane];
            hold0 = Hc[(size_t)fug0 * 32 + lane];
            hold1 = Hc[(size_t)fug1 * 32 + lane];
        }

        // partial dot over this warp's k-half (256 k = 128 pair-quads)
        float2 az0 = {0.f, 0.f}, az1 = {0.f, 0.f};
        float2 ar0 = {0.f, 0.f}, ar1 = {0.f, 0.f};
        float2 ah0 = {0.f, 0.f}, ah1 = {0.f, 0.f};

        const float2* hp = Hc + (size_t)(kh * 256) * 32 + lane;

#pragma unroll 4
        for (int kq = 0; kq < 128; kq++) {
            float2 h0 = hp[(size_t)(2 * kq) * 32];
            float2 h1 = hp[(size_t)(2 * kq + 1) * 32];
            float4 uz0 = UZ0[kq], uz1 = UZ1[kq];
            float4 ur0 = UR0[kq], ur1 = UR1[kq];
            float4 uh0 = UH0[kq], uh1 = UH1[kq];
            fma2(az0, make_float2(uz0.x, uz0.y), h0);
            fma2(az0, make_float2(uz0.z, uz0.w), h1);
            fma2(az1, make_float2(uz1.x, uz1.y), h0);
            fma2(az1, make_float2(uz1.z, uz1.w), h1);
            fma2(ar0, make_float2(ur0.x, ur0.y), h0);
            fma2(ar0, make_float2(ur0.z, ur0.w), h1);
            fma2(ar1, make_float2(ur1.x, ur1.y), h0);
            fma2(ar1, make_float2(ur1.z, ur1.w), h1);
            fma2(ah0, make_float2(uh0.x, uh0.y), h0);
            fma2(ah0, make_float2(uh0.z, uh0.w), h1);
            fma2(ah1, make_float2(uh1.x, uh1.y), h0);
            fma2(ah1, make_float2(uh1.z, uh1.w), h1);
        }

        part[w][0][lane] = az0; part[w][1][lane] = az1;
        part[w][2][lane] = ar0; part[w][3][lane] = ar1;
        part[w][4][lane] = ah0; part[w][5][lane] = ah1;
        __syncthreads();

        if (w < 4) {
            // combine k-halves from partner warps 2w and 2w+1
            float2 paz0 = part[2 * w][0][lane], qaz0 = part[2 * w + 1][0][lane];
            float2 paz1 = part[2 * w][1][lane], qaz1 = part[2 * w + 1][1][lane];
            float2 par0 = part[2 * w][2][lane], qar0 = part[2 * w + 1][2][lane];
            float2 par1 = part[2 * w][3][lane], qar1 = part[2 * w + 1][3][lane];
            float2 pah0 = part[2 * w][4][lane], qah0 = part[2 * w + 1][4][lane];
            float2 pah1 = part[2 * w][5][lane], qah1 = part[2 * w + 1][5][lane];
            float azx0 = paz0.x + qaz0.x, azy0 = paz0.y + qaz0.y;
            float azx1 = paz1.x + qaz1.x, azy1 = paz1.y + qaz1.y;
            float arx0 = par0.x + qar0.x, ary0 = par0.y + qar0.y;
            float arx1 = par1.x + qar1.x, ary1 = par1.y + qar1.y;
            float ahx0 = pah0.x + qah0.x, ahy0 = pah0.y + qah0.y;
            float ahx1 = pah1.x + qah1.x, ahy1 = pah1.y + qah1.y;

            // unit 0 of pair
            float z0x = 1.0f / (1.0f + expf(-(xz0.x + azx0 + brz0)));
            float z0y = 1.0f / (1.0f + expf(-(xz0.y + azy0 + brz0)));
            float r0x = 1.0f / (1.0f + expf(-(xr0.x + arx0 + brr0)));
            float r0y = 1.0f / (1.0f + expf(-(xr0.y + ary0 + brr0)));
            float hh0x = tanhf(xh0.x + r0x * (ahx0 + brh0));
            float hh0y = tanhf(xh0.y + r0y * (ahy0 + brh0));
            float hn0x = z0x * hold0.x + (1.0f - z0x) * hh0x;
            float hn0y = z0y * hold0.y + (1.0f - z0y) * hh0y;
            // unit 1 of pair
            float z1x = 1.0f / (1.0f + expf(-(xz1.x + azx1 + brz1)));
            float z1y = 1.0f / (1.0f + expf(-(xz1.y + azy1 + brz1)));
            float r1x = 1.0f / (1.0f + expf(-(xr1.x + arx1 + brr1)));
            float r1y = 1.0f / (1.0f + expf(-(xr1.y + ary1 + brr1)));
            float hh1x = tanhf(xh1.x + r1x * (ahx1 + brh1));
            float hh1y = tanhf(xh1.y + r1y * (ahy1 + brh1));
            float hn1x = z1x * hold1.x + (1.0f - z1x) * hh1x;
            float hn1y = z1y * hold1.y + (1.0f - z1y) * hh1y;

            Hn[(size_t)fug0 * 32 + lane] = make_float2(hn0x, hn0y);
            Hn[(size_t)fug1 * 32 + lane] = make_float2(hn1x, hn1y);

            int b0 = 2 * lane;
            hout[((size_t)b0 * T_ + tt) * U_ + fug0]       = hn0x;
            hout[((size_t)(b0 + 1) * T_ + tt) * U_ + fug0] = hn0y;
            hout[((size_t)b0 * T_ + tt) * U_ + fug1]       = hn1x;
            hout[((size_t)(b0 + 1) * T_ + tt) * U_ + fug1] = hn1y;
        }

        dir_barrier(dir, (unsigned)(s + 1));
    }
}

// ---------------------------------------------------------------------------
// Epilogue: y = concat(hf,hb) + resid; LayerNorm over last dim (1024)
// ---------------------------------------------------------------------------
__global__ void __launch_bounds__(256) ln_kernel(
    const float* __restrict__ gamma, const float* __restrict__ beta,
    float* __restrict__ out)
{
    __shared__ float red[2][8];
    int row = blockIdx.x;       // b*T + t
    int tid = threadIdx.x;
    int c   = tid * 4;

    const float* hsrc = (tid < 128)
        ? (g_hf + (size_t)row * U_ + c)
        : (g_hb + (size_t)row * U_ + (c - U_));
    float4 h4 = *(const float4*)hsrc;
    float4 r4 = *(const float4*)(g_resid + (size_t)row * P_ + c);

    float y0 = h4.x + r4.x, y1 = h4.y + r4.y, y2 = h4.z + r4.z, y3 = h4.w + r4.w;
    float s  = y0 + y1 + y2 + y3;
    float s2 = y0 * y0 + y1 * y1 + y2 * y2 + y3 * y3;

#pragma unroll
    for (int off = 16; off > 0; off >>= 1) {
        s  += __shfl_xor_sync(0xFFFFFFFFu, s,  off);
        s2 += __shfl_xor_sync(0xFFFFFFFFu, s2, off);
    }
    int wid = tid >> 5, lane = tid & 31;
    if (lane == 0) { red[0][wid] = s; red[1][wid] = s2; }
    __syncthreads();
    s = 0.f; s2 = 0.f;
#pragma unroll
    for (int i = 0; i < 8; i++) { s += red[0][i]; s2 += red[1][i]; }

    float mu  = s * (1.0f / 1024.0f);
    float var = s2 * (1.0f / 1024.0f) - mu * mu;
    float inv = rsqrtf(var + EPS_);

    float4 g4 = *(const float4*)(gamma + c);
    float4 b4 = *(const float4*)(beta + c);
    float4 o;
    o.x = g4.x * (y0 - mu) * inv + b4.x;
    o.y = g4.y * (y1 - mu) * inv + b4.y;
    o.z = g4.z * (y2 - mu) * inv + b4.z;
    o.w = g4.w * (y3 - mu) * inv + b4.w;
    *(float4*)(out + (size_t)row * P_ + c) = o;
}

// ---------------------------------------------------------------------------
extern "C" void kernel_launch(void* const* d_in, const int* in_sizes, int n_in,
                              void* d_out, int out_size) {
    const float* x     = (const float*)d_in[0];
    const float* Wf    = (const float*)d_in[1];
    const float* Uf    = (const float*)d_in[2];
    const float* bf    = (const float*)d_in[3];
    const float* Wb    = (const float*)d_in[4];
    const float* Ub    = (const float*)d_in[5];
    const float* bb    = (const float*)d_in[6];
    const float* Wp    = (const float*)d_in[7];
    const float* gamma = (const float*)d_in[8];
    const float* beta  = (const float*)d_in[9];
    float* out = (float*)d_out;

    const int gru_smem = 24 * 512 * 8 + 8 * 6 * 32 * 8;  // 110592 B
    cudaFuncSetAttribute(gru_kernel, cudaFuncAttributeMaxDynamicSharedMemorySize, gru_smem);

    init_kernel<<<64, 256>>>();

    dim3 g1(1024, 24);  // 65536/64 x 1536/64
    dim3 g2(1024, 16);  // 65536/64 x 1024/64
    gemm_kernel<<<g1, 256>>>(x, Wf, bf, G_, 0);
    gemm_kernel<<<g1, 256>>>(x, Wb, bb, G_, 1);
    gemm_kernel<<<g2, 256>>>(x, Wp, nullptr, P_, 2);

    gru_kernel<<<128, 256, gru_smem>>>(Uf, Ub, bf, bb);

    ln_kernel<<<B_ * T_, 256>>>(gamma, beta, out);
}

// round 5
// speedup vs baseline: 1.5208x; 1.5208x over previous
#include <cuda_runtime.h>
#include <cstdint>

#define B_   64
#define T_   1024
#define F_   256
#define U_   512
#define G_   1536             // 3*U
#define P_   1024             // 2*U
#define GB_  (G_*B_)          // 98304
#define HB_  (U_*B_)          // 32768 floats per h ping-pong buffer
#define EPS_ 1e-3f

// ---------------------------------------------------------------------------
// Scratch: __device__ globals (allocation-free per harness rules)
// ---------------------------------------------------------------------------
__device__ float g_xwf[(size_t)T_ * G_ * B_];   // [T][G][B]  x@Wf + bi_f
__device__ float g_xwb[(size_t)T_ * G_ * B_];   // [T][G][B]  x@Wb + bi_b
__device__ float g_resid[(size_t)B_ * T_ * P_]; // [B*T][P]   x@Wp
__device__ float g_hf[(size_t)B_ * T_ * U_];    // [B][T][U]
__device__ float g_hb[(size_t)B_ * T_ * U_];    // [B][T][U]
// h ping-pong: [dir][parity] of float2 [256 kp][64 b]; element {h[2kp][b], h[2kp+1][b]}
__device__ float g_hbuf[2 * 2 * HB_];
__device__ unsigned g_barc[2];                  // barrier arrive counters
__device__ unsigned g_barg[2];                  // barrier generations

// ---------------------------------------------------------------------------
// f32x2 packed FMA (Blackwell dual-fp32; only reachable via PTX)
// ---------------------------------------------------------------------------
__device__ __forceinline__ void fma2(float2& d, float2 a, float2 b) {
    unsigned long long& dd = reinterpret_cast<unsigned long long&>(d);
    unsigned long long& aa = reinterpret_cast<unsigned long long&>(a);
    unsigned long long& bb = reinterpret_cast<unsigned long long&>(b);
    asm("fma.rn.f32x2 %0, %1, %2, %0;" : "+l"(dd) : "l"(aa), "l"(bb));
}
__device__ __forceinline__ float2 dup2(float x) { return make_float2(x, x); }

// ---------------------------------------------------------------------------
// Init: zero h0 buffers + barrier state (graph replays reuse globals)
// ---------------------------------------------------------------------------
__global__ void init_kernel() {
    int idx = blockIdx.x * blockDim.x + threadIdx.x;
    int stride = gridDim.x * blockDim.x;
    for (int i = idx; i < 2 * 2 * HB_; i += stride) g_hbuf[i] = 0.0f;
    if (idx < 2) { g_barc[idx] = 0u; g_barg[idx] = 0u; }
}

// ---------------------------------------------------------------------------
// fp32 GEMM: A[BT,256] x Bw[256,N].  64x64 tile, BK=16, 256 threads.
//  mode 0 -> g_xwf [t][g][b] (+bias), mode 1 -> g_xwb, mode 2 -> g_resid [r][n]
// ---------------------------------------------------------------------------
__global__ void __launch_bounds__(256) gemm_kernel(
    const float* __restrict__ A, const float* __restrict__ Bw,
    const float* __restrict__ bias, int N, int mode)
{
    __shared__ float As[16][64];
    __shared__ float Bs[16][64];

    int tid  = threadIdx.x;
    int tx   = tid & 15;
    int ty   = tid >> 4;
    int row0 = blockIdx.x * 64;
    int col0 = blockIdx.y * 64;

    int lrow = tid >> 2;        // A: row within tile
    int lkq  = (tid & 3) * 4;   // A: k quad
    int lk   = tid >> 4;        // B: k row
    int lnq  = (tid & 15) * 4;  // B: col quad

    float2 acc[4][2];
#pragma unroll
    for (int i = 0; i < 4; i++) { acc[i][0] = make_float2(0.f, 0.f); acc[i][1] = make_float2(0.f, 0.f); }

    for (int k0 = 0; k0 < F_; k0 += 16) {
        float4 av = *(const float4*)(A + (size_t)(row0 + lrow) * F_ + k0 + lkq);
        As[lkq + 0][lrow] = av.x;
        As[lkq + 1][lrow] = av.y;
        As[lkq + 2][lrow] = av.z;
        As[lkq + 3][lrow] = av.w;
        *(float4*)(&Bs[lk][lnq]) = *(const float4*)(Bw + (size_t)(k0 + lk) * N + col0 + lnq);
        __syncthreads();

#pragma unroll
        for (int kk = 0; kk < 16; kk++) {
            float4 a4 = *(const float4*)(&As[kk][ty * 4]);
            float4 b4 = *(const float4*)(&Bs[kk][tx * 4]);
            float2 bp0 = make_float2(b4.x, b4.y);
            float2 bp1 = make_float2(b4.z, b4.w);
            float aa[4] = {a4.x, a4.y, a4.z, a4.w};
#pragma unroll
            for (int i = 0; i < 4; i++) {
                float2 ad = dup2(aa[i]);
                fma2(acc[i][0], ad, bp0);
                fma2(acc[i][1], ad, bp1);
            }
        }
        __syncthreads();
    }

    if (mode == 2) {
#pragma unroll
        for (int i = 0; i < 4; i++) {
            int r = row0 + ty * 4 + i;
            int c = col0 + tx * 4;
            g_resid[(size_t)r * P_ + c + 0] = acc[i][0].x;
            g_resid[(size_t)r * P_ + c + 1] = acc[i][0].y;
            g_resid[(size_t)r * P_ + c + 2] = acc[i][1].x;
            g_resid[(size_t)r * P_ + c + 3] = acc[i][1].y;
        }
    } else {
        float* outp = (mode == 1) ? g_xwb : g_xwf;
#pragma unroll
        for (int i = 0; i < 4; i++) {
            int r = row0 + ty * 4 + i;
            int b = r >> 10;       // r = b*1024 + t
            int t = r & 1023;
            int c = col0 + tx * 4;
            float v[4] = {acc[i][0].x, acc[i][0].y, acc[i][1].x, acc[i][1].y};
#pragma unroll
            for (int j = 0; j < 4; j++) {
                int g = c + j;
                outp[(size_t)t * GB_ + (size_t)g * B_ + b] = v[j] + bias[g];
            }
        }
    }
}

// ---------------------------------------------------------------------------
// Per-direction grid barrier (64 blocks each, all co-resident)
// ---------------------------------------------------------------------------
__device__ __forceinline__ void dir_barrier(int dir, unsigned target) {
    __syncthreads();
    if (threadIdx.x == 0) {
        __threadfence();
        unsigned prev = atomicAdd(&g_barc[dir], 1u);
        if (prev == 63u) {
            g_barc[dir] = 0u;
            __threadfence();
            atomicAdd(&g_barg[dir], 1u);
        } else {
            volatile unsigned* vg = &g_barg[dir];
            while (*vg < target) { __nanosleep(16); }
            __threadfence();
        }
    }
    __syncthreads();
}

// ---------------------------------------------------------------------------
// GRU recurrence v4 (k-pair fma2, zero-MOV operands).
// 128 blocks: 0..63 forward, 64..127 backward. Block owns 8 hidden units.
// 256 threads = 8 warps; warp w: unit pair up=w>>1, k-half kh=w&1.
// H layout: float2 H[kp][b] = {h[2kp][b], h[2kp+1][b]} -> one LDG.128 gives
// the k-pair for two adjacent batches, aligned .xy/.zw halves for fma.rn.f32x2.
// U in smem non-duplicated: LDS.128 gives 4 k = two aligned operand pairs.
// Dynamic smem: U 48KB + partials 12KB = 60KB.
// ---------------------------------------------------------------------------
__global__ void __launch_bounds__(256) gru_kernel(
    const float* __restrict__ Ufm, const float* __restrict__ Ubm,
    const float* __restrict__ bfv, const float* __restrict__ bbv)
{
    extern __shared__ float smem_[];
    float* Us = smem_;                                  // [24][512]
    float2 (*part)[6][32] = (float2 (*)[6][32])(smem_ + 24 * 512);  // [8][6][32]

    int tid = threadIdx.x;
    int dir = blockIdx.x >> 6;
    int jb  = blockIdx.x & 63;

    const float* Um    = dir ? Ubm : Ufm;
    const float* brv   = (dir ? bbv : bfv) + G_;   // recurrent bias b[1]
    const float* xw    = dir ? g_xwb : g_xwf;
    float*       hout  = dir ? g_hb  : g_hf;
    float*       hbase = g_hbuf + (size_t)dir * 2 * HB_;

    // Load U slice: column c=(gate,uu) -> Um[:, gate*512 + jb*8 + uu]
    for (int idx = tid; idx < 24 * 512; idx += 256) {
        int c = idx >> 9;
        int k = idx & 511;
        int g  = c >> 3;
        int uu = c & 7;
        Us[c * 512 + k] = Um[(size_t)k * G_ + g * U_ + jb * 8 + uu];
    }

    int w    = tid >> 5;
    int lane = tid & 31;
    int kh   = w & 1;          // k half: kp in [kh*128, kh*128+128)
    int up   = w >> 1;         // unit pair 0..3
    int ul0  = up * 2, ul1 = ul0 + 1;

    // compute-role U pointers (float4 over k, offset by k-half)
    const float4* UZ0 = (const float4*)(Us + (0 * 8 + ul0) * 512 + kh * 256);
    const float4* UZ1 = (const float4*)(Us + (0 * 8 + ul1) * 512 + kh * 256);
    const float4* UR0 = (const float4*)(Us + (1 * 8 + ul0) * 512 + kh * 256);
    const float4* UR1 = (const float4*)(Us + (1 * 8 + ul1) * 512 + kh * 256);
    const float4* UH0 = (const float4*)(Us + (2 * 8 + ul0) * 512 + kh * 256);
    const float4* UH1 = (const float4*)(Us + (2 * 8 + ul1) * 512 + kh * 256);

    // finalize-role (warps 0..3): units 2w, 2w+1
    int fug0 = jb * 8 + 2 * w;
    int fug1 = fug0 + 1;
    float brz0 = 0.f, brz1 = 0.f, brr0 = 0.f, brr1 = 0.f, brh0 = 0.f, brh1 = 0.f;
    if (w < 4) {
        brz0 = brv[fug0];          brz1 = brv[fug1];
        brr0 = brv[U_ + fug0];     brr1 = brv[U_ + fug1];
        brh0 = brv[2 * U_ + fug0]; brh1 = brv[2 * U_ + fug1];
    }

    __syncthreads();

    for (int s = 0; s < T_; s++) {
        int tt = dir ? (T_ - 1 - s) : s;

        int par = s & 1;
        const float2* Hc = (const float2*)(hbase + (size_t)par * HB_);        // [256][64]
        float2*       Hn = (float2*)(hbase + (size_t)(par ^ 1) * HB_);

        // finalize warps prefetch input projections + previous h (indep of dots)
        float2 xz0, xz1, xr0, xr1, xh0, xh1;
        float4 holdq;
        if (w < 4) {
            const float2* XW2 = (const float2*)(xw + (size_t)tt * GB_);
            xz0 = XW2[(size_t)(0 * U_ + fug0) * 32 + lane];
            xz1 = XW2[(size_t)(0 * U_ + fug1) * 32 + lane];
            xr0 = XW2[(size_t)(1 * U_ + fug0) * 32 + lane];
            xr1 = XW2[(size_t)(1 * U_ + fug1) * 32 + lane];
            xh0 = XW2[(size_t)(2 * U_ + fug0) * 32 + lane];
            xh1 = XW2[(size_t)(2 * U_ + fug1) * 32 + lane];
            // {h[fug0][b0], h[fug1][b0], h[fug0][b1], h[fug1][b1]}
            holdq = *(const float4*)(Hc + (size_t)(fug0 >> 1) * 64 + 2 * lane);
        }

        // partial dots over this warp's k-half.
        // acc[c][b] holds {even-k partial, odd-k partial} for batch b.
        float2 az00 = {0.f,0.f}, az01 = {0.f,0.f}, az10 = {0.f,0.f}, az11 = {0.f,0.f};
        float2 ar00 = {0.f,0.f}, ar01 = {0.f,0.f}, ar10 = {0.f,0.f}, ar11 = {0.f,0.f};
        float2 ah00 = {0.f,0.f}, ah01 = {0.f,0.f}, ah10 = {0.f,0.f}, ah11 = {0.f,0.f};

        const float2* hp = Hc + (size_t)(kh * 128) * 64 + 2 * lane;

#pragma unroll 2
        for (int i = 0; i < 64; i++) {
            // two k-pairs (4 k), each LDG.128 covers both batches
            float4 hA = *(const float4*)(hp + (size_t)(2 * i) * 64);      // kp: b0=.xy b1=.zw
            float4 hB = *(const float4*)(hp + (size_t)(2 * i + 1) * 64);  // kp+1
            float2 hA0 = make_float2(hA.x, hA.y), hA1 = make_float2(hA.z, hA.w);
            float2 hB0 = make_float2(hB.x, hB.y), hB1 = make_float2(hB.z, hB.w);
            float4 uz0 = UZ0[i], uz1 = UZ1[i];
            float4 ur0 = UR0[i], ur1 = UR1[i];
            float4 uh0 = UH0[i], uh1 = UH1[i];
            fma2(az00, make_float2(uz0.x, uz0.y), hA0);
            fma2(az00, make_float2(uz0.z, uz0.w), hB0);
            fma2(az01, make_float2(uz0.x, uz0.y), hA1);
            fma2(az01, make_float2(uz0.z, uz0.w), hB1);
            fma2(az10, make_float2(uz1.x, uz1.y), hA0);
            fma2(az10, make_float2(uz1.z, uz1.w), hB0);
            fma2(az11, make_float2(uz1.x, uz1.y), hA1);
            fma2(az11, make_float2(uz1.z, uz1.w), hB1);
            fma2(ar00, make_float2(ur0.x, ur0.y), hA0);
            fma2(ar00, make_float2(ur0.z, ur0.w), hB0);
            fma2(ar01, make_float2(ur0.x, ur0.y), hA1);
            fma2(ar01, make_float2(ur0.z, ur0.w), hB1);
            fma2(ar10, make_float2(ur1.x, ur1.y), hA0);
            fma2(ar10, make_float2(ur1.z, ur1.w), hB0);
            fma2(ar11, make_float2(ur1.x, ur1.y), hA1);
            fma2(ar11, make_float2(ur1.z, ur1.w), hB1);
            fma2(ah00, make_float2(uh0.x, uh0.y), hA0);
            fma2(ah00, make_float2(uh0.z, uh0.w), hB0);
            fma2(ah01, make_float2(uh0.x, uh0.y), hA1);
            fma2(ah01, make_float2(uh0.z, uh0.w), hB1);
            fma2(ah10, make_float2(uh1.x, uh1.y), hA0);
            fma2(ah10, make_float2(uh1.z, uh1.w), hB0);
            fma2(ah11, make_float2(uh1.x, uh1.y), hA1);
            fma2(ah11, make_float2(uh1.z, uh1.w), hB1);
        }

        // fold k-parity, store partials as {b0, b1} per (col)
        part[w][0][lane] = make_float2(az00.x + az00.y, az01.x + az01.y);
        part[w][1][lane] = make_float2(az10.x + az10.y, az11.x + az11.y);
        part[w][2][lane] = make_float2(ar00.x + ar00.y, ar01.x + ar01.y);
        part[w][3][lane] = make_float2(ar10.x + ar10.y, ar11.x + ar11.y);
        part[w][4][lane] = make_float2(ah00.x + ah00.y, ah01.x + ah01.y);
        part[w][5][lane] = make_float2(ah10.x + ah10.y, ah11.x + ah11.y);
        __syncthreads();

        if (w < 4) {
            // combine k-halves from partner warps 2w and 2w+1
            float2 paz0 = part[2 * w][0][lane], qaz0 = part[2 * w + 1][0][lane];
            float2 paz1 = part[2 * w][1][lane], qaz1 = part[2 * w + 1][1][lane];
            float2 par0 = part[2 * w][2][lane], qar0 = part[2 * w + 1][2][lane];
            float2 par1 = part[2 * w][3][lane], qar1 = part[2 * w + 1][3][lane];
            float2 pah0 = part[2 * w][4][lane], qah0 = part[2 * w + 1][4][lane];
            float2 pah1 = part[2 * w][5][lane], qah1 = part[2 * w + 1][5][lane];
            float azx0 = paz0.x + qaz0.x, azy0 = paz0.y + qaz0.y;
            float azx1 = paz1.x + qaz1.x, azy1 = paz1.y + qaz1.y;
            float arx0 = par0.x + qar0.x, ary0 = par0.y + qar0.y;
            float arx1 = par1.x + qar1.x, ary1 = par1.y + qar1.y;
            float ahx0 = pah0.x + qah0.x, ahy0 = pah0.y + qah0.y;
            float ahx1 = pah1.x + qah1.x, ahy1 = pah1.y + qah1.y;

            float hold0x = holdq.x, hold1x = holdq.y;   // b0
            float hold0y = holdq.z, hold1y = holdq.w;   // b1

            // unit 0 of pair (x suffix = batch b0, y = batch b1)
            float z0x = 1.0f / (1.0f + expf(-(xz0.x + azx0 + brz0)));
            float z0y = 1.0f / (1.0f + expf(-(xz0.y + azy0 + brz0)));
            float r0x = 1.0f / (1.0f + expf(-(xr0.x + arx0 + brr0)));
            float r0y = 1.0f / (1.0f + expf(-(xr0.y + ary0 + brr0)));
            float hh0x = tanhf(xh0.x + r0x * (ahx0 + brh0));
            float hh0y = tanhf(xh0.y + r0y * (ahy0 + brh0));
            float hn0x = z0x * hold0x + (1.0f - z0x) * hh0x;
            float hn0y = z0y * hold0y + (1.0f - z0y) * hh0y;
            // unit 1 of pair
            float z1x = 1.0f / (1.0f + expf(-(xz1.x + azx1 + brz1)));
            float z1y = 1.0f / (1.0f + expf(-(xz1.y + azy1 + brz1)));
            float r1x = 1.0f / (1.0f + expf(-(xr1.x + arx1 + brr1)));
            float r1y = 1.0f / (1.0f + expf(-(xr1.y + ary1 + brr1)));
            float hh1x = tanhf(xh1.x + r1x * (ahx1 + brh1));
            float hh1y = tanhf(xh1.y + r1y * (ahy1 + brh1));
            float hn1x = z1x * hold1x + (1.0f - z1x) * hh1x;
            float hn1y = z1y * hold1y + (1.0f - z1y) * hh1y;

            // write next h: {unit0,unit1} k-pair for batches b0,b1 = one float4
            *(float4*)(Hn + (size_t)(fug0 >> 1) * 64 + 2 * lane) =
                make_float4(hn0x, hn1x, hn0y, hn1y);

            int b0 = 2 * lane;
            hout[((size_t)b0 * T_ + tt) * U_ + fug0]       = hn0x;
            hout[((size_t)(b0 + 1) * T_ + tt) * U_ + fug0] = hn0y;
            hout[((size_t)b0 * T_ + tt) * U_ + fug1]       = hn1x;
            hout[((size_t)(b0 + 1) * T_ + tt) * U_ + fug1] = hn1y;
        }

        dir_barrier(dir, (unsigned)(s + 1));
    }
}

// ---------------------------------------------------------------------------
// Epilogue: y = concat(hf,hb) + resid; LayerNorm over last dim (1024)
// ---------------------------------------------------------------------------
__global__ void __launch_bounds__(256) ln_kernel(
    const float* __restrict__ gamma, const float* __restrict__ beta,
    float* __restrict__ out)
{
    __shared__ float red[2][8];
    int row = blockIdx.x;       // b*T + t
    int tid = threadIdx.x;
    int c   = tid * 4;

    const float* hsrc = (tid < 128)
        ? (g_hf + (size_t)row * U_ + c)
        : (g_hb + (size_t)row * U_ + (c - U_));
    float4 h4 = *(const float4*)hsrc;
    float4 r4 = *(const float4*)(g_resid + (size_t)row * P_ + c);

    float y0 = h4.x + r4.x, y1 = h4.y + r4.y, y2 = h4.z + r4.z, y3 = h4.w + r4.w;
    float s  = y0 + y1 + y2 + y3;
    float s2 = y0 * y0 + y1 * y1 + y2 * y2 + y3 * y3;

#pragma unroll
    for (int off = 16; off > 0; off >>= 1) {
        s  += __shfl_xor_sync(0xFFFFFFFFu, s,  off);
        s2 += __shfl_xor_sync(0xFFFFFFFFu, s2, off);
    }
    int wid = tid >> 5, lane = tid & 31;
    if (lane == 0) { red[0][wid] = s; red[1][wid] = s2; }
    __syncthreads();
    s = 0.f; s2 = 0.f;
#pragma unroll
    for (int i = 0; i < 8; i++) { s += red[0][i]; s2 += red[1][i]; }

    float mu  = s * (1.0f / 1024.0f);
    float var = s2 * (1.0f / 1024.0f) - mu * mu;
    float inv = rsqrtf(var + EPS_);

    float4 g4 = *(const float4*)(gamma + c);
    float4 b4 = *(const float4*)(beta + c);
    float4 o;
    o.x = g4.x * (y0 - mu) * inv + b4.x;
    o.y = g4.y * (y1 - mu) * inv + b4.y;
    o.z = g4.z * (y2 - mu) * inv + b4.z;
    o.w = g4.w * (y3 - mu) * inv + b4.w;
    *(float4*)(out + (size_t)row * P_ + c) = o;
}

// ---------------------------------------------------------------------------
extern "C" void kernel_launch(void* const* d_in, const int* in_sizes, int n_in,
                              void* d_out, int out_size) {
    const float* x     = (const float*)d_in[0];
    const float* Wf    = (const float*)d_in[1];
    const float* Uf    = (const float*)d_in[2];
    const float* bf    = (const float*)d_in[3];
    const float* Wb    = (const float*)d_in[4];
    const float* Ub    = (const float*)d_in[5];
    const float* bb    = (const float*)d_in[6];
    const float* Wp    = (const float*)d_in[7];
    const float* gamma = (const float*)d_in[8];
    const float* beta  = (const float*)d_in[9];
    float* out = (float*)d_out;

    const int gru_smem = 24 * 512 * 4 + 8 * 6 * 32 * 8;  // 61440 B
    cudaFuncSetAttribute(gru_kernel, cudaFuncAttributeMaxDynamicSharedMemorySize, gru_smem);

    init_kernel<<<64, 256>>>();

    dim3 g1(1024, 24);  // 65536/64 x 1536/64
    dim3 g2(1024, 16);  // 65536/64 x 1024/64
    gemm_kernel<<<g1, 256>>>(x, Wf, bf, G_, 0);
    gemm_kernel<<<g1, 256>>>(x, Wb, bb, G_, 1);
    gemm_kernel<<<g2, 256>>>(x, Wp, nullptr, P_, 2);

    gru_kernel<<<128, 256, gru_smem>>>(Uf, Ub, bf, bb);

    ln_kernel<<<B_ * T_, 256>>>(gamma, beta, out);
}

// round 6
// speedup vs baseline: 2.5456x; 1.6739x over previous
#include <cuda_runtime.h>
#include <cstdint>

#define B_   64
#define T_   1024
#define F_   256
#define U_   512
#define G_   1536             // 3*U
#define P_   1024             // 2*U
#define GB_  (G_*B_)          // 98304
#define HB_  (U_*B_)          // 32768 floats per h ping-pong buffer
#define EPS_ 1e-3f

// ---------------------------------------------------------------------------
// Scratch: __device__ globals (allocation-free per harness rules)
// ---------------------------------------------------------------------------
__device__ float g_xwf[(size_t)T_ * G_ * B_];   // [T][G][B]  x@Wf + bi_f
__device__ float g_xwb[(size_t)T_ * G_ * B_];   // [T][G][B]  x@Wb + bi_b
__device__ float g_resid[(size_t)B_ * T_ * P_]; // [B*T][P]   x@Wp
__device__ float g_hf[(size_t)B_ * T_ * U_];    // [B][T][U]
__device__ float g_hb[(size_t)B_ * T_ * U_];    // [B][T][U]
// h ping-pong: [dir][parity], float2 H[kp=256][b=64], element {h[2kp][b], h[2kp+1][b]}
__device__ float g_hbuf[2 * 2 * HB_];
__device__ unsigned g_barc[2];                  // barrier arrive counters
__device__ unsigned g_barg[2];                  // barrier generations

// ---------------------------------------------------------------------------
// f32x2 packed FMA (Blackwell dual-fp32; only reachable via PTX)
// ---------------------------------------------------------------------------
__device__ __forceinline__ void fma2(float2& d, float2 a, float2 b) {
    unsigned long long& dd = reinterpret_cast<unsigned long long&>(d);
    unsigned long long& aa = reinterpret_cast<unsigned long long&>(a);
    unsigned long long& bb = reinterpret_cast<unsigned long long&>(b);
    asm("fma.rn.f32x2 %0, %1, %2, %0;" : "+l"(dd) : "l"(aa), "l"(bb));
}
__device__ __forceinline__ float2 dup2(float x) { return make_float2(x, x); }

// ---------------------------------------------------------------------------
__global__ void init_kernel() {
    int idx = blockIdx.x * blockDim.x + threadIdx.x;
    int stride = gridDim.x * blockDim.x;
    for (int i = idx; i < 2 * 2 * HB_; i += stride) g_hbuf[i] = 0.0f;
    if (idx < 2) { g_barc[idx] = 0u; g_barg[idx] = 0u; }
}

// ---------------------------------------------------------------------------
// GEMM core: 64x64 tile, BK=16, 256 threads. Computes C = A[64rows,256] x Bw
// Caller-specific epilogues below.
// ---------------------------------------------------------------------------
__device__ __forceinline__ void gemm_tile(
    const float* __restrict__ A, const float* __restrict__ Bw, int N,
    int row0, int col0, float2 acc[4][2],
    float (*As)[64], float (*Bs)[64])
{
    int tid  = threadIdx.x;
    int tx   = tid & 15;
    int ty   = tid >> 4;
    int lrow = tid >> 2;
    int lkq  = (tid & 3) * 4;
    int lk   = tid >> 4;
    int lnq  = (tid & 15) * 4;

#pragma unroll
    for (int i = 0; i < 4; i++) { acc[i][0] = make_float2(0.f, 0.f); acc[i][1] = make_float2(0.f, 0.f); }

    for (int k0 = 0; k0 < F_; k0 += 16) {
        float4 av = *(const float4*)(A + (size_t)(row0 + lrow) * F_ + k0 + lkq);
        As[lkq + 0][lrow] = av.x;
        As[lkq + 1][lrow] = av.y;
        As[lkq + 2][lrow] = av.z;
        As[lkq + 3][lrow] = av.w;
        *(float4*)(&Bs[lk][lnq]) = *(const float4*)(Bw + (size_t)(k0 + lk) * N + col0 + lnq);
        __syncthreads();

#pragma unroll
        for (int kk = 0; kk < 16; kk++) {
            float4 a4 = *(const float4*)(&As[kk][ty * 4]);
            float4 b4 = *(const float4*)(&Bs[kk][tx * 4]);
            float2 bp0 = make_float2(b4.x, b4.y);
            float2 bp1 = make_float2(b4.z, b4.w);
            float aa[4] = {a4.x, a4.y, a4.z, a4.w};
#pragma unroll
            for (int i = 0; i < 4; i++) {
                float2 ad = dup2(aa[i]);
                fma2(acc[i][0], ad, bp0);
                fma2(acc[i][1], ad, bp1);
            }
        }
        __syncthreads();
    }
}

// Fused xw GEMMs (Wf and Wb): blockIdx.y in [0,48). y<24 -> Wf, else Wb.
__global__ void __launch_bounds__(256) gemm_xw_kernel(
    const float* __restrict__ x,
    const float* __restrict__ Wf, const float* __restrict__ Wb,
    const float* __restrict__ bf, const float* __restrict__ bb)
{
    __shared__ float As[16][64];
    __shared__ float Bs[16][64];
    int ysel = blockIdx.y >= 24;
    const float* Bw   = ysel ? Wb : Wf;
    const float* bias = ysel ? bb : bf;
    float* outp       = ysel ? g_xwb : g_xwf;
    int row0 = blockIdx.x * 64;
    int col0 = (blockIdx.y - (ysel ? 24 : 0)) * 64;

    float2 acc[4][2];
    gemm_tile(x, Bw, G_, row0, col0, acc, As, Bs);

    int tx = threadIdx.x & 15, ty = threadIdx.x >> 4;
#pragma unroll
    for (int i = 0; i < 4; i++) {
        int r = row0 + ty * 4 + i;
        int b = r >> 10;
        int t = r & 1023;
        int c = col0 + tx * 4;
        float v[4] = {acc[i][0].x, acc[i][0].y, acc[i][1].x, acc[i][1].y};
#pragma unroll
        for (int j = 0; j < 4; j++) {
            int g = c + j;
            outp[(size_t)t * GB_ + (size_t)g * B_ + b] = v[j] + bias[g];
        }
    }
}

// Residual projection GEMM (Wp)
__global__ void __launch_bounds__(256) gemm_p_kernel(
    const float* __restrict__ x, const float* __restrict__ Wp)
{
    __shared__ float As[16][64];
    __shared__ float Bs[16][64];
    int row0 = blockIdx.x * 64;
    int col0 = blockIdx.y * 64;

    float2 acc[4][2];
    gemm_tile(x, Wp, P_, row0, col0, acc, As, Bs);

    int tx = threadIdx.x & 15, ty = threadIdx.x >> 4;
#pragma unroll
    for (int i = 0; i < 4; i++) {
        int r = row0 + ty * 4 + i;
        int c = col0 + tx * 4;
        g_resid[(size_t)r * P_ + c + 0] = acc[i][0].x;
        g_resid[(size_t)r * P_ + c + 1] = acc[i][0].y;
        g_resid[(size_t)r * P_ + c + 2] = acc[i][1].x;
        g_resid[(size_t)r * P_ + c + 3] = acc[i][1].y;
    }
}

// ---------------------------------------------------------------------------
// GRU recurrence v6 (dedup h reads; k-pair zero-MOV fma2; split-phase barrier).
// 128 blocks: 0..63 forward, 64..127 backward. Block owns 8 hidden units.
// 512 threads = 16 warps: warp w -> (kw = w>>1 in 0..7: k-eighth, bh = w&1:
// batch half). Each warp computes partials for ALL 24 U-columns over its
// (64 k x 32 batch) tile => every h element read exactly once per block.
// H layout: float2 H[kp][b] = {h[2kp][b], h[2kp+1][b]}.
// SMEM: U 48KB [c][k] + partials 96KB [16][24][32] float2 = 144KB.
// ---------------------------------------------------------------------------
__global__ void __launch_bounds__(512) gru_kernel(
    const float* __restrict__ Ufm, const float* __restrict__ Ubm,
    const float* __restrict__ bfv, const float* __restrict__ bbv)
{
    extern __shared__ float smem_[];
    float*  Us   = smem_;                              // [24][512]
    float2* part = (float2*)(smem_ + 24 * 512);        // [16][24][32]
#define PART(w, c, l) part[(((w) * 24 + (c)) << 5) + (l)]

    int tid = threadIdx.x;
    int dir = blockIdx.x >> 6;
    int jb  = blockIdx.x & 63;

    const float* Um    = dir ? Ubm : Ufm;
    const float* brv   = (dir ? bbv : bfv) + G_;   // recurrent bias b[1]
    const float* xw    = dir ? g_xwb : g_xwf;
    float*       hout  = dir ? g_hb  : g_hf;
    float*       hbase = g_hbuf + (size_t)dir * 2 * HB_;

    // Load U slice: column c = gate*8+uu -> Um[:, gate*512 + jb*8 + uu]
    for (int idx = tid; idx < 24 * 512; idx += 512) {
        int c = idx >> 9;
        int k = idx & 511;
        int g  = c >> 3;
        int uu = c & 7;
        Us[c * 512 + k] = Um[(size_t)k * G_ + g * U_ + jb * 8 + uu];
    }

    int w    = tid >> 5;
    int lane = tid & 31;
    int kw   = w >> 1;          // k-eighth: k in [kw*64, kw*64+64)
    int bh   = w & 1;           // batch half
    int b    = bh * 32 + lane;

    // finalize role (warps 0..3): units fug0=jb*8+2w, fug1=fug0+1
    int fug0 = jb * 8 + 2 * w;
    int fug1 = fug0 + 1;
    float brz0 = 0.f, brz1 = 0.f, brr0 = 0.f, brr1 = 0.f, brh0 = 0.f, brh1 = 0.f;
    if (w < 4) {
        brz0 = brv[fug0];          brz1 = brv[fug1];
        brr0 = brv[U_ + fug0];     brr1 = brv[U_ + fug1];
        brh0 = brv[2 * U_ + fug0]; brh1 = brv[2 * U_ + fug1];
    }

    const float4* U4 = (const float4*)Us;   // index: c*128 + kw*16 + i

    __syncthreads();

    for (int s = 0; s < T_; s++) {
        int tt = dir ? (T_ - 1 - s) : s;

        int par = s & 1;
        const float2* Hc = (const float2*)(hbase + (size_t)par * HB_);   // [256][64]
        float2*       Hn = (float2*)(hbase + (size_t)(par ^ 1) * HB_);

        // finalize warps prefetch xw + previous-h (independent of dots)
        float xza, xzb, xz1a, xz1b, xra, xrb, xr1a, xr1b, xha, xhb, xh1a, xh1b;
        float2 hva, hvb;
        if (w < 4) {
            const float* XW = xw + (size_t)tt * GB_;
            xza  = XW[(0 * U_ + fug0) * B_ + lane];
            xzb  = XW[(0 * U_ + fug0) * B_ + lane + 32];
            xz1a = XW[(0 * U_ + fug1) * B_ + lane];
            xz1b = XW[(0 * U_ + fug1) * B_ + lane + 32];
            xra  = XW[(1 * U_ + fug0) * B_ + lane];
            xrb  = XW[(1 * U_ + fug0) * B_ + lane + 32];
            xr1a = XW[(1 * U_ + fug1) * B_ + lane];
            xr1b = XW[(1 * U_ + fug1) * B_ + lane + 32];
            xha  = XW[(2 * U_ + fug0) * B_ + lane];
            xhb  = XW[(2 * U_ + fug0) * B_ + lane + 32];
            xh1a = XW[(2 * U_ + fug1) * B_ + lane];
            xh1b = XW[(2 * U_ + fug1) * B_ + lane + 32];
            hva = Hc[(size_t)(fug0 >> 1) * 64 + lane];        // {h[fug0][lane], h[fug1][lane]}
            hvb = Hc[(size_t)(fug0 >> 1) * 64 + lane + 32];
        }

        // ---- partial dots: all 24 cols over (64 k x own batch) ----
        float2 acc[24];
#pragma unroll
        for (int c = 0; c < 24; c++) acc[c] = make_float2(0.f, 0.f);

        const float2* hpp = Hc + (size_t)(kw * 32) * 64 + b;
        int ub = kw * 16;

        float2 h0 = hpp[0];
        float2 h1 = hpp[64];
#pragma unroll 4
        for (int i = 0; i < 16; i++) {
            float2 nh0, nh1;
            if (i < 15) {
                nh0 = hpp[(size_t)(2 * i + 2) * 64];
                nh1 = hpp[(size_t)(2 * i + 3) * 64];
            }
#pragma unroll
            for (int c = 0; c < 24; c++) {
                float4 u = U4[c * 128 + ub + i];
                fma2(acc[c], make_float2(u.x, u.y), h0);
                fma2(acc[c], make_float2(u.z, u.w), h1);
            }
            h0 = nh0; h1 = nh1;
        }

#pragma unroll
        for (int c = 0; c < 24; c++) PART(w, c, lane) = acc[c];
        __syncthreads();

        float hn0a, hn0b, hn1a, hn1b;
        if (w < 4) {
            // combine 8 k-partials per (gate,unit,batch-half); fold even/odd k
            float sa[6], sb[6];   // [gate*2 + du]
#pragma unroll
            for (int g = 0; g < 3; g++) {
#pragma unroll
                for (int du = 0; du < 2; du++) {
                    int c = g * 8 + 2 * w + du;
                    float va = 0.f, vb = 0.f;
#pragma unroll
                    for (int k8 = 0; k8 < 8; k8++) {
                        float2 pa = PART(2 * k8,     c, lane);
                        float2 pb = PART(2 * k8 + 1, c, lane);
                        va += pa.x + pa.y;
                        vb += pb.x + pb.y;
                    }
                    sa[g * 2 + du] = va;
                    sb[g * 2 + du] = vb;
                }
            }

            // unit 0 (du=0): batches a=lane, b=lane+32
            float z0a = 1.0f / (1.0f + expf(-(xza + sa[0] + brz0)));
            float z0b = 1.0f / (1.0f + expf(-(xzb + sb[0] + brz0)));
            float r0a = 1.0f / (1.0f + expf(-(xra + sa[2] + brr0)));
            float r0b = 1.0f / (1.0f + expf(-(xrb + sb[2] + brr0)));
            float hh0a = tanhf(xha + r0a * (sa[4] + brh0));
            float hh0b = tanhf(xhb + r0b * (sb[4] + brh0));
            hn0a = z0a * hva.x + (1.0f - z0a) * hh0a;
            hn0b = z0b * hvb.x + (1.0f - z0b) * hh0b;
            // unit 1 (du=1)
            float z1a = 1.0f / (1.0f + expf(-(xz1a + sa[1] + brz1)));
            float z1b = 1.0f / (1.0f + expf(-(xz1b + sb[1] + brz1)));
            float r1a = 1.0f / (1.0f + expf(-(xr1a + sa[3] + brr1)));
            float r1b = 1.0f / (1.0f + expf(-(xr1b + sb[3] + brr1)));
            float hh1a = tanhf(xh1a + r1a * (sa[5] + brh1));
            float hh1b = tanhf(xh1b + r1b * (sb[5] + brh1));
            hn1a = z1a * hva.y + (1.0f - z1a) * hh1a;
            hn1b = z1b * hvb.y + (1.0f - z1b) * hh1b;

            // write next h (k-pair layout, coalesced float2)
            Hn[(size_t)(fug0 >> 1) * 64 + lane]      = make_float2(hn0a, hn1a);
            Hn[(size_t)(fug0 >> 1) * 64 + lane + 32] = make_float2(hn0b, hn1b);
        }
        __syncthreads();   // all Hn stores complete before release

        // split-phase barrier: arrive, overlap hout stores with the wait
        if (tid == 0) {
            __threadfence();
            unsigned prev = atomicAdd(&g_barc[dir], 1u);
            if (prev == 63u) {
                g_barc[dir] = 0u;
                __threadfence();
                atomicAdd(&g_barg[dir], 1u);
            }
        }
        if (w < 4) {   // scattered per-timestep output stores (independent of barrier)
            hout[((size_t)lane * T_ + tt) * U_ + fug0]        = hn0a;
            hout[((size_t)lane * T_ + tt) * U_ + fug1]        = hn1a;
            hout[((size_t)(lane + 32) * T_ + tt) * U_ + fug0] = hn0b;
            hout[((size_t)(lane + 32) * T_ + tt) * U_ + fug1] = hn1b;
        }
        if (tid == 0) {
            volatile unsigned* vg = &g_barg[dir];
            unsigned target = (unsigned)(s + 1);
            while (*vg < target) { __nanosleep(16); }
            __threadfence();   // acquire ordering + L1D invalidate
        }
        __syncthreads();
    }
#undef PART
}

// ---------------------------------------------------------------------------
// Epilogue: y = concat(hf,hb) + resid; LayerNorm over last dim (1024)
// ---------------------------------------------------------------------------
__global__ void __launch_bounds__(256) ln_kernel(
    const float* __restrict__ gamma, const float* __restrict__ beta,
    float* __restrict__ out)
{
    __shared__ float red[2][8];
    int row = blockIdx.x;       // b*T + t
    int tid = threadIdx.x;
    int c   = tid * 4;

    const float* hsrc = (tid < 128)
        ? (g_hf + (size_t)row * U_ + c)
        : (g_hb + (size_t)row * U_ + (c - U_));
    float4 h4 = *(const float4*)hsrc;
    float4 r4 = *(const float4*)(g_resid + (size_t)row * P_ + c);

    float y0 = h4.x + r4.x, y1 = h4.y + r4.y, y2 = h4.z + r4.z, y3 = h4.w + r4.w;
    float s  = y0 + y1 + y2 + y3;
    float s2 = y0 * y0 + y1 * y1 + y2 * y2 + y3 * y3;

#pragma unroll
    for (int off = 16; off > 0; off >>= 1) {
        s  += __shfl_xor_sync(0xFFFFFFFFu, s,  off);
        s2 += __shfl_xor_sync(0xFFFFFFFFu, s2, off);
    }
    int wid = tid >> 5, lane = tid & 31;
    if (lane == 0) { red[0][wid] = s; red[1][wid] = s2; }
    __syncthreads();
    s = 0.f; s2 = 0.f;
#pragma unroll
    for (int i = 0; i < 8; i++) { s += red[0][i]; s2 += red[1][i]; }

    float mu  = s * (1.0f / 1024.0f);
    float var = s2 * (1.0f / 1024.0f) - mu * mu;
    float inv = rsqrtf(var + EPS_);

    float4 g4 = *(const float4*)(gamma + c);
    float4 b4 = *(const float4*)(beta + c);
    float4 o;
    o.x = g4.x * (y0 - mu) * inv + b4.x;
    o.y = g4.y * (y1 - mu) * inv + b4.y;
    o.z = g4.z * (y2 - mu) * inv + b4.z;
    o.w = g4.w * (y3 - mu) * inv + b4.w;
    *(float4*)(out + (size_t)row * P_ + c) = o;
}

// ---------------------------------------------------------------------------
extern "C" void kernel_launch(void* const* d_in, const int* in_sizes, int n_in,
                              void* d_out, int out_size) {
    const float* x     = (const float*)d_in[0];
    const float* Wf    = (const float*)d_in[1];
    const float* Uf    = (const float*)d_in[2];
    const float* bf    = (const float*)d_in[3];
    const float* Wb    = (const float*)d_in[4];
    const float* Ub    = (const float*)d_in[5];
    const float* bb    = (const float*)d_in[6];
    const float* Wp    = (const float*)d_in[7];
    const float* gamma = (const float*)d_in[8];
    const float* beta  = (const float*)d_in[9];
    float* out = (float*)d_out;

    const int gru_smem = 24 * 512 * 4 + 16 * 24 * 32 * 8;  // 49152 + 98304 = 147456 B
    cudaFuncSetAttribute(gru_kernel, cudaFuncAttributeMaxDynamicSharedMemorySize, gru_smem);

    init_kernel<<<64, 256>>>();
    gemm_xw_kernel<<<dim3(1024, 48), 256>>>(x, Wf, Wb, bf, bb);
    gemm_p_kernel<<<dim3(1024, 16), 256>>>(x, Wp);
    gru_kernel<<<128, 512, gru_smem>>>(Uf, Ub, bf, bb);
    ln_kernel<<<B_ * T_, 256>>>(gamma, beta, out);
}

// round 7
// speedup vs baseline: 2.7746x; 1.0899x over previous
#include <cuda_runtime.h>
#include <cstdint>

#define B_   64
#define T_   1024
#define F_   256
#define U_   512
#define G_   1536             // 3*U
#define P_   1024             // 2*U
#define GB_  (G_*B_)          // 98304
#define HB_  (U_*B_)          // 32768 floats per h ping-pong buffer
#define EPS_ 1e-3f

// ---------------------------------------------------------------------------
// Scratch: __device__ globals (allocation-free per harness rules)
// ---------------------------------------------------------------------------
__device__ float g_xwf[(size_t)T_ * G_ * B_];   // [T][G][B]  x@Wf + bi_f
__device__ float g_xwb[(size_t)T_ * G_ * B_];   // [T][G][B]  x@Wb + bi_b
__device__ float g_resid[(size_t)B_ * T_ * P_]; // [B*T][P]   x@Wp
__device__ float g_hf[(size_t)B_ * T_ * U_];    // [B][T][U]
__device__ float g_hb[(size_t)B_ * T_ * U_];    // [B][T][U]
// h ping-pong: [dir][parity], float2 H[kp=256][b=64], element {h[2kp][b], h[2kp+1][b]}
__device__ float g_hbuf[2 * 2 * HB_];
__device__ unsigned g_barc[2];                  // barrier arrive counters
__device__ unsigned g_barg[2];                  // barrier generations

// ---------------------------------------------------------------------------
// f32x2 packed FMA (Blackwell dual-fp32; only reachable via PTX)
// ---------------------------------------------------------------------------
__device__ __forceinline__ void fma2(float2& d, float2 a, float2 b) {
    unsigned long long& dd = reinterpret_cast<unsigned long long&>(d);
    unsigned long long& aa = reinterpret_cast<unsigned long long&>(a);
    unsigned long long& bb = reinterpret_cast<unsigned long long&>(b);
    asm("fma.rn.f32x2 %0, %1, %2, %0;" : "+l"(dd) : "l"(aa), "l"(bb));
}
__device__ __forceinline__ float2 dup2(float x) { return make_float2(x, x); }

// ---------------------------------------------------------------------------
__global__ void init_kernel() {
    int idx = blockIdx.x * blockDim.x + threadIdx.x;
    int stride = gridDim.x * blockDim.x;
    for (int i = idx; i < 2 * 2 * HB_; i += stride) g_hbuf[i] = 0.0f;
    if (idx < 2) { g_barc[idx] = 0u; g_barg[idx] = 0u; }
}

// ---------------------------------------------------------------------------
// GEMM core: 64x64 tile, BK=16, 256 threads.
// ---------------------------------------------------------------------------
__device__ __forceinline__ void gemm_tile(
    const float* __restrict__ A, const float* __restrict__ Bw, int N,
    int row0, int col0, float2 acc[4][2],
    float (*As)[64], float (*Bs)[64])
{
    int tid  = threadIdx.x;
    int tx   = tid & 15;
    int ty   = tid >> 4;
    int lrow = tid >> 2;
    int lkq  = (tid & 3) * 4;
    int lk   = tid >> 4;
    int lnq  = (tid & 15) * 4;

#pragma unroll
    for (int i = 0; i < 4; i++) { acc[i][0] = make_float2(0.f, 0.f); acc[i][1] = make_float2(0.f, 0.f); }

    for (int k0 = 0; k0 < F_; k0 += 16) {
        float4 av = *(const float4*)(A + (size_t)(row0 + lrow) * F_ + k0 + lkq);
        As[lkq + 0][lrow] = av.x;
        As[lkq + 1][lrow] = av.y;
        As[lkq + 2][lrow] = av.z;
        As[lkq + 3][lrow] = av.w;
        *(float4*)(&Bs[lk][lnq]) = *(const float4*)(Bw + (size_t)(k0 + lk) * N + col0 + lnq);
        __syncthreads();

#pragma unroll
        for (int kk = 0; kk < 16; kk++) {
            float4 a4 = *(const float4*)(&As[kk][ty * 4]);
            float4 b4 = *(const float4*)(&Bs[kk][tx * 4]);
            float2 bp0 = make_float2(b4.x, b4.y);
            float2 bp1 = make_float2(b4.z, b4.w);
            float aa[4] = {a4.x, a4.y, a4.z, a4.w};
#pragma unroll
            for (int i = 0; i < 4; i++) {
                float2 ad = dup2(aa[i]);
                fma2(acc[i][0], ad, bp0);
                fma2(acc[i][1], ad, bp1);
            }
        }
        __syncthreads();
    }
}

// Fused xw GEMMs (Wf and Wb): blockIdx.y in [0,48). y<24 -> Wf, else Wb.
__global__ void __launch_bounds__(256) gemm_xw_kernel(
    const float* __restrict__ x,
    const float* __restrict__ Wf, const float* __restrict__ Wb,
    const float* __restrict__ bf, const float* __restrict__ bb)
{
    __shared__ float As[16][64];
    __shared__ float Bs[16][64];
    int ysel = blockIdx.y >= 24;
    const float* Bw   = ysel ? Wb : Wf;
    const float* bias = ysel ? bb : bf;
    float* outp       = ysel ? g_xwb : g_xwf;
    int row0 = blockIdx.x * 64;
    int col0 = (blockIdx.y - (ysel ? 24 : 0)) * 64;

    float2 acc[4][2];
    gemm_tile(x, Bw, G_, row0, col0, acc, As, Bs);

    int tx = threadIdx.x & 15, ty = threadIdx.x >> 4;
#pragma unroll
    for (int i = 0; i < 4; i++) {
        int r = row0 + ty * 4 + i;
        int b = r >> 10;
        int t = r & 1023;
        int c = col0 + tx * 4;
        float v[4] = {acc[i][0].x, acc[i][0].y, acc[i][1].x, acc[i][1].y};
#pragma unroll
        for (int j = 0; j < 4; j++) {
            int g = c + j;
            outp[(size_t)t * GB_ + (size_t)g * B_ + b] = v[j] + bias[g];
        }
    }
}

// Residual projection GEMM (Wp)
__global__ void __launch_bounds__(256) gemm_p_kernel(
    const float* __restrict__ x, const float* __restrict__ Wp)
{
    __shared__ float As[16][64];
    __shared__ float Bs[16][64];
    int row0 = blockIdx.x * 64;
    int col0 = blockIdx.y * 64;

    float2 acc[4][2];
    gemm_tile(x, Wp, P_, row0, col0, acc, As, Bs);

    int tx = threadIdx.x & 15, ty = threadIdx.x >> 4;
#pragma unroll
    for (int i = 0; i < 4; i++) {
        int r = row0 + ty * 4 + i;
        int c = col0 + tx * 4;
        g_resid[(size_t)r * P_ + c + 0] = acc[i][0].x;
        g_resid[(size_t)r * P_ + c + 1] = acc[i][0].y;
        g_resid[(size_t)r * P_ + c + 2] = acc[i][1].x;
        g_resid[(size_t)r * P_ + c + 3] = acc[i][1].y;
    }
}

// ---------------------------------------------------------------------------
// GRU recurrence v7.
// 128 blocks: 0..63 forward, 64..127 backward. Block owns 8 hidden units.
// 512 threads = 16 warps: warp w -> (kw = w>>1: k-eighth, bh = w&1: batch half).
// Compute: warp computes partials for ALL 24 U-cols over its (64k x 32b) tile
//          (every h element read exactly once per block), folded to scalar.
// Finalize: SAME warp decomposition reused as (unit uf = w>>1, batch-half bh):
//          each thread finishes one (unit, batch) -> low register pressure,
//          all 16 warps busy.
// h prefetch: 2 outer iterations (~300 cyc) ahead to cover L2 latency
// (L1 is invalidated each step by the barrier's gpu-scope fence).
// SMEM: U 48KB [24][512] + partials 48KB [16][24][32] float = 96KB.
// ---------------------------------------------------------------------------
__global__ void __launch_bounds__(512) gru_kernel(
    const float* __restrict__ Ufm, const float* __restrict__ Ubm,
    const float* __restrict__ bfv, const float* __restrict__ bbv)
{
    extern __shared__ float smem_[];
    float* Us   = smem_;                         // [24][512]
    float* part = smem_ + 24 * 512;              // [16][24][32] folded
#define PART(w, c, l) part[(((w) * 24 + (c)) << 5) + (l)]

    int tid = threadIdx.x;
    int dir = blockIdx.x >> 6;
    int jb  = blockIdx.x & 63;

    const float* Um    = dir ? Ubm : Ufm;
    const float* brv   = (dir ? bbv : bfv) + G_;   // recurrent bias b[1]
    const float* xw    = dir ? g_xwb : g_xwf;
    float*       hout  = dir ? g_hb  : g_hf;
    float*       hbase = g_hbuf + (size_t)dir * 2 * HB_;

    // Load U slice: column c = gate*8+uu -> Um[:, gate*512 + jb*8 + uu]
    for (int idx = tid; idx < 24 * 512; idx += 512) {
        int c = idx >> 9;
        int k = idx & 511;
        int g  = c >> 3;
        int uu = c & 7;
        Us[c * 512 + k] = Um[(size_t)k * G_ + g * U_ + jb * 8 + uu];
    }

    int w    = tid >> 5;
    int lane = tid & 31;
    int kw   = w >> 1;          // compute: k-eighth; finalize: unit index uf
    int bh   = w & 1;           // batch half (both roles)
    int b    = bh * 32 + lane;  // batch (both roles)

    int uf   = kw;              // finalize unit 0..7
    int fug  = jb * 8 + uf;
    float brz = brv[fug];
    float brr = brv[U_ + fug];
    float brh = brv[2 * U_ + fug];

    const float4* U4 = (const float4*)Us;   // index: c*128 + kw*16 + i
    int ub = kw * 16;

    __syncthreads();

    for (int s = 0; s < T_; s++) {
        int tt = dir ? (T_ - 1 - s) : s;

        int par = s & 1;
        const float2* Hc = (const float2*)(hbase + (size_t)par * HB_);   // [256][64]
        float*        HnF = hbase + (size_t)(par ^ 1) * HB_;             // float view

        // per-thread finalize operands (independent of dots; issue early)
        const float* XW = xw + (size_t)tt * GB_;
        float xz = XW[(0 * U_ + fug) * B_ + b];
        float xr = XW[(1 * U_ + fug) * B_ + b];
        float xh = XW[(2 * U_ + fug) * B_ + b];
        float2 hv = Hc[(size_t)(fug >> 1) * 64 + b];
        float hold = (uf & 1) ? hv.y : hv.x;

        // ---- partial dots: all 24 cols over (64 k x own batch) ----
        float2 acc[24];
#pragma unroll
        for (int c = 0; c < 24; c++) acc[c] = make_float2(0.f, 0.f);

        const float2* hpp = Hc + (size_t)(kw * 32) * 64 + b;

        float2 h0 = hpp[0];
        float2 h1 = hpp[64];
        float2 h2 = hpp[128];
        float2 h3 = hpp[192];
#pragma unroll
        for (int i = 0; i < 16; i += 2) {
            float2 n0, n1, n2, n3;
            if (i < 14) {
                n0 = hpp[(size_t)(2 * i + 4) * 64];
                n1 = hpp[(size_t)(2 * i + 5) * 64];
                n2 = hpp[(size_t)(2 * i + 6) * 64];
                n3 = hpp[(size_t)(2 * i + 7) * 64];
            }
#pragma unroll
            for (int c = 0; c < 24; c++) {
                float4 u = U4[c * 128 + ub + i];
                fma2(acc[c], make_float2(u.x, u.y), h0);
                fma2(acc[c], make_float2(u.z, u.w), h1);
            }
#pragma unroll
            for (int c = 0; c < 24; c++) {
                float4 u = U4[c * 128 + ub + i + 1];
                fma2(acc[c], make_float2(u.x, u.y), h2);
                fma2(acc[c], make_float2(u.z, u.w), h3);
            }
            h0 = n0; h1 = n1; h2 = n2; h3 = n3;
        }

#pragma unroll
        for (int c = 0; c < 24; c++) PART(w, c, lane) = acc[c].x + acc[c].y;
        __syncthreads();

        // ---- finalize: all 16 warps; thread -> (unit uf, batch b) ----
        float sz = 0.f, sr = 0.f, sh = 0.f;
#pragma unroll
        for (int k8 = 0; k8 < 8; k8++) {
            int wp = 2 * k8 + bh;
            sz += PART(wp, 0 * 8 + uf, lane);
            sr += PART(wp, 1 * 8 + uf, lane);
            sh += PART(wp, 2 * 8 + uf, lane);
        }
        float z  = 1.0f / (1.0f + expf(-(xz + sz + brz)));
        float r  = 1.0f / (1.0f + expf(-(xr + sr + brr)));
        float hh = tanhf(xh + r * (sh + brh));
        float hn = z * hold + (1.0f - z) * hh;

        // next-h store (k-pair float layout: [kp][b][2])
        HnF[(((size_t)(fug >> 1) * 64 + b) << 1) + (uf & 1)] = hn;
        __syncthreads();   // all Hn stores complete before release

        // split-phase barrier: arrive, overlap hout store with the wait
        if (tid == 0) {
            __threadfence();
            unsigned prev = atomicAdd(&g_barc[dir], 1u);
            if (prev == 63u) {
                g_barc[dir] = 0u;
                __threadfence();
                atomicAdd(&g_barg[dir], 1u);
            }
        }
        // scattered per-timestep output store (independent of barrier)
        hout[((size_t)b * T_ + tt) * U_ + fug] = hn;

        if (tid == 0) {
            volatile unsigned* vg = &g_barg[dir];
            unsigned target = (unsigned)(s + 1);
            while (*vg < target) { __nanosleep(16); }
            __threadfence();   // acquire + L1D invalidate
        }
        __syncthreads();
    }
#undef PART
}

// ---------------------------------------------------------------------------
// Epilogue: y = concat(hf,hb) + resid; LayerNorm over last dim (1024)
// ---------------------------------------------------------------------------
__global__ void __launch_bounds__(256) ln_kernel(
    const float* __restrict__ gamma, const float* __restrict__ beta,
    float* __restrict__ out)
{
    __shared__ float red[2][8];
    int row = blockIdx.x;       // b*T + t
    int tid = threadIdx.x;
    int c   = tid * 4;

    const float* hsrc = (tid < 128)
        ? (g_hf + (size_t)row * U_ + c)
        : (g_hb + (size_t)row * U_ + (c - U_));
    float4 h4 = *(const float4*)hsrc;
    float4 r4 = *(const float4*)(g_resid + (size_t)row * P_ + c);

    float y0 = h4.x + r4.x, y1 = h4.y + r4.y, y2 = h4.z + r4.z, y3 = h4.w + r4.w;
    float s  = y0 + y1 + y2 + y3;
    float s2 = y0 * y0 + y1 * y1 + y2 * y2 + y3 * y3;

#pragma unroll
    for (int off = 16; off > 0; off >>= 1) {
        s  += __shfl_xor_sync(0xFFFFFFFFu, s,  off);
        s2 += __shfl_xor_sync(0xFFFFFFFFu, s2, off);
    }
    int wid = tid >> 5, lane = tid & 31;
    if (lane == 0) { red[0][wid] = s; red[1][wid] = s2; }
    __syncthreads();
    s = 0.f; s2 = 0.f;
#pragma unroll
    for (int i = 0; i < 8; i++) { s += red[0][i]; s2 += red[1][i]; }

    float mu  = s * (1.0f / 1024.0f);
    float var = s2 * (1.0f / 1024.0f) - mu * mu;
    float inv = rsqrtf(var + EPS_);

    float4 g4 = *(const float4*)(gamma + c);
    float4 b4 = *(const float4*)(beta + c);
    float4 o;
    o.x = g4.x * (y0 - mu) * inv + b4.x;
    o.y = g4.y * (y1 - mu) * inv + b4.y;
    o.z = g4.z * (y2 - mu) * inv + b4.z;
    o.w = g4.w * (y3 - mu) * inv + b4.w;
    *(float4*)(out + (size_t)row * P_ + c) = o;
}

// ---------------------------------------------------------------------------
extern "C" void kernel_launch(void* const* d_in, const int* in_sizes, int n_in,
                              void* d_out, int out_size) {
    const float* x     = (const float*)d_in[0];
    const float* Wf    = (const float*)d_in[1];
    const float* Uf    = (const float*)d_in[2];
    const float* bf    = (const float*)d_in[3];
    const float* Wb    = (const float*)d_in[4];
    const float* Ub    = (const float*)d_in[5];
    const float* bb    = (const float*)d_in[6];
    const float* Wp    = (const float*)d_in[7];
    const float* gamma = (const float*)d_in[8];
    const float* beta  = (const float*)d_in[9];
    float* out = (float*)d_out;

    const int gru_smem = 24 * 512 * 4 + 16 * 24 * 32 * 4;  // 49152 + 49152 = 98304 B
    cudaFuncSetAttribute(gru_kernel, cudaFuncAttributeMaxDynamicSharedMemorySize, gru_smem);

    init_kernel<<<64, 256>>>();
    gemm_xw_kernel<<<dim3(1024, 48), 256>>>(x, Wf, Wb, bf, bb);
    gemm_p_kernel<<<dim3(1024, 16), 256>>>(x, Wp);
    gru_kernel<<<128, 512, gru_smem>>>(Uf, Ub, bf, bb);
    ln_kernel<<<B_ * T_, 256>>>(gamma, beta, out);
}